// round 4
// baseline (speedup 1.0000x reference)
#include <cuda_runtime.h>

// Find_Ring_Bonds: B=16384 molecules, A=80 atoms, D=4 neighbors, R=10 rings, S=8.
// edges: [B, A, D] float32 (integer-valued, -1 = null neighbor)
// rings: [B, R, S] int32 (-1 = padding)
// out:   [B, A, D] float32 (1.0 if bond (a, e[a][d]) lies in some ring, else 0.0)
//
// Algorithm: per molecule, build atom_rings[a] = 10-bit mask of rings containing
// atom a (80 shared atomicOr ops; R*S == A == 80 so one entry per thread).
// Bond is a ring bond iff (atom_rings[a] & atom_rings[e]) != 0 and e != -1.
//
// Pure streaming workload: ~47 MB total traffic, no FLOPs -> HBM-bound.

static constexpr int A = 80;
static constexpr int D = 4;
static constexpr int R = 10;
static constexpr int S = 8;
static constexpr int MOLS_PER_BLOCK = 4;
static constexpr int THREADS = MOLS_PER_BLOCK * A;   // 320

__global__ __launch_bounds__(THREADS, 4)
void find_ring_bonds_kernel(const float* __restrict__ edges,
                            const int*   __restrict__ rings,
                            float*       __restrict__ out)
{
    __shared__ unsigned int atom_rings[MOLS_PER_BLOCK][A];

    const int tid = threadIdx.x;
    const int m = tid / A;          // local molecule index 0..3
    const int a = tid % A;          // atom index / ring-entry index 0..79
    const long mol = (long)blockIdx.x * MOLS_PER_BLOCK + m;

    // Phase 0: zero the per-molecule ring-set masks (one word per thread).
    atom_rings[m][a] = 0u;
    __syncthreads();

    // Phase 1: scatter ring membership. Thread 'a' owns ring entry 'a'
    // (ring r = a>>3, slot a&7). Coalesced int32 loads.
    {
        const int r = a >> 3;                // ring index 0..9
        const int atom = rings[mol * (R * S) + a];
        if (atom >= 0)
            atomicOr(&atom_rings[m][atom], 1u << r);
    }
    __syncthreads();

    // Phase 2: each thread handles one atom's 4 neighbor slots (float4 I/O).
    const unsigned int my_rings = atom_rings[m][a];
    const float4 e4 = reinterpret_cast<const float4*>(edges)[mol * A + a];

    const int e0 = (int)e4.x;
    const int e1 = (int)e4.y;
    const int e2 = (int)e4.z;
    const int e3 = (int)e4.w;

    float4 o;
    o.x = (e0 >= 0 && (my_rings & atom_rings[m][e0])) ? 1.0f : 0.0f;
    o.y = (e1 >= 0 && (my_rings & atom_rings[m][e1])) ? 1.0f : 0.0f;
    o.z = (e2 >= 0 && (my_rings & atom_rings[m][e2])) ? 1.0f : 0.0f;
    o.w = (e3 >= 0 && (my_rings & atom_rings[m][e3])) ? 1.0f : 0.0f;

    reinterpret_cast<float4*>(out)[mol * A + a] = o;
}

extern "C" void kernel_launch(void* const* d_in, const int* in_sizes, int n_in,
                              void* d_out, int out_size)
{
    const float* edges = (const float*)d_in[0];   // [B, A, D] float32
    const int*   rings = (const int*)d_in[1];     // [B, R, S] int32
    float* out = (float*)d_out;                   // [B, A, D, 1] float32

    const int batch = out_size / (A * D);         // 16384
    const int grid = (batch + MOLS_PER_BLOCK - 1) / MOLS_PER_BLOCK;

    find_ring_bonds_kernel<<<grid, THREADS>>>(edges, rings, out);
}